// round 17
// baseline (speedup 1.0000x reference)
#include <cuda_runtime.h>
#include <cstdint>

typedef unsigned long long u64;

#define BATCH 32
#define HID   64
#define CHUNK 2048
#define CMASK (CHUNK-1)
#define LOGC  11

__device__ __forceinline__ u64 fma2(u64 a, u64 b, u64 c){
    u64 d; asm("fma.rn.f32x2 %0, %1, %2, %3;" : "=l"(d) : "l"(a), "l"(b), "l"(c)); return d;
}
__device__ __forceinline__ u64 add2(u64 a, u64 b){
    u64 d; asm("add.rn.f32x2 %0, %1, %2;" : "=l"(d) : "l"(a), "l"(b)); return d;
}
__device__ __forceinline__ u64 mul2(u64 a, u64 b){
    u64 d; asm("mul.rn.f32x2 %0, %1, %2;" : "=l"(d) : "l"(a), "l"(b)); return d;
}
__device__ __forceinline__ u64 pack2(float lo, float hi){
    u64 d; asm("mov.b64 %0, {%1, %2};" : "=l"(d) : "f"(lo), "f"(hi)); return d;
}
__device__ __forceinline__ float hsum2(u64 a){
    float lo, hi; asm("mov.b64 {%0,%1}, %2;" : "=f"(lo), "=f"(hi) : "l"(a)); return lo + hi;
}
__device__ __forceinline__ float ex2f(float a){
    float d; asm("ex2.approx.f32 %0, %1;" : "=f"(d) : "f"(a)); return d;
}
__device__ __forceinline__ float rcpf(float a){
    float d; asm("rcp.approx.f32 %0, %1;" : "=f"(d) : "f"(a)); return d;
}

#define NEG_L2E (-1.4426950408889634f)
#define TWO_L2E  2.8853900817779268f

// One CTA per batch row. 128 threads; pair (2i,2i+1) owns hidden unit i.
// Lane p=0: full 64-dot for r; p=1: full 64-dot for z; BOTH lanes: full
// 64-dot for n (duplicated: FMA issue hides in stall shadows; chain matters).
// Only z crosses lanes (shfl consumed at the final FMA, slack-hidden).
// R16 form + x-term SOFTWARE PIPELINING: block k+1's x-terms are computed
// during block k's late steps (independent work, sunk into MUFU slack), so
// NO x LDS/FMA sits in any post-bar window. Wrap-indexed loads keep the
// loop branch-free.
__global__ void __launch_bounds__(128, 1)
gru_kernel(const float* __restrict__ x, const float* __restrict__ w_ih,
           const float* __restrict__ w_hh, const float* __restrict__ b_ih,
           const float* __restrict__ b_hh, float* __restrict__ states, int T)
{
    __shared__ __align__(16) float hbuf[2][HID];
    __shared__ __align__(16) float xs[2][CHUNK];

    const int tid = threadIdx.x;
    const int b   = blockIdx.x;
    const int i   = tid >> 1;
    const int p   = tid & 1;
    const int ia  = i + 64 * p;        // r-row (p=0) or z-row (p=1)
    const int in_ = 128 + i;           // n-row

    // weights into registers, PRE-SCALED (packed f32x2)
    u64 wa[32];                         // own-gate row * (-log2e)
    {
        const u64 s = pack2(NEG_L2E, NEG_L2E);
        const u64* was = (const u64*)(w_hh + (size_t)ia * 64);
        #pragma unroll
        for (int q = 0; q < 32; q++) wa[q] = mul2(was[q], s);
    }
    u64 wn[32];                         // full n-row * (2*log2e)
    {
        const u64 s = pack2(TWO_L2E, TWO_L2E);
        const u64* wns = (const u64*)(w_hh + (size_t)in_ * 64);
        #pragma unroll
        for (int q = 0; q < 32; q++) wn[q] = mul2(wns[q], s);
    }

    // fused activation constants
    const float wihaL = w_ih[ia] * NEG_L2E;
    const float caL   = (b_hh[ia] + b_ih[ia]) * NEG_L2E;
    const float wihn2 = w_ih[in_] * TWO_L2E;
    const float bihn2 = b_ih[in_] * TWO_L2E;
    const float bhhn2 = b_hh[in_] * TWO_L2E;

    const float* xrow = x + (size_t)b * T;

    if (tid < HID) hbuf[0][tid] = 0.0f;
    {
        const float4* src = (const float4*)xrow;
        float4* dst = (float4*)xs[0];
        #pragma unroll
        for (int q = 0; q < CHUNK / 4 / 128; q++) dst[tid + q * 128] = src[tid + q * 128];
    }
    __syncthreads();

    float* sp = states + ((size_t)b * T) * HID + i;   // additive pointer
    float hprev = 0.0f;
    const int nch = T >> LOGC;
    const u64 nb0 = pack2(bhhn2, 0.0f);      // n-acc init (bias pre-added)

    // one GRU step; x-terms precomputed by caller
    auto step = [&](const float* hc, float* hd, float xac, float xn2) {
        const float hm1 = hprev - 1.0f;           // off-chain

        // load h once (16 x LDS.128), reuse for both dots
        ulonglong2 hv[16];
        const ulonglong2* hs = (const ulonglong2*)hc;
        #pragma unroll
        for (int q = 0; q < 16; q++) hv[q] = hs[q];

        // own-gate 64-dot; acc a0 seeded with xac -> reduce yields ex2 arg
        u64 a0 = pack2(xac, 0.0f);
        u64 a1=0,a2=0,a3=0,a4=0,a5=0,a6=0,a7=0;
        #pragma unroll
        for (int q = 0; q < 4; q++) {
            a0 = fma2(hv[4*q].x,   wa[8*q],   a0);
            a1 = fma2(hv[4*q].y,   wa[8*q+1], a1);
            a2 = fma2(hv[4*q+1].x, wa[8*q+2], a2);
            a3 = fma2(hv[4*q+1].y, wa[8*q+3], a3);
            a4 = fma2(hv[4*q+2].x, wa[8*q+4], a4);
            a5 = fma2(hv[4*q+2].y, wa[8*q+5], a5);
            a6 = fma2(hv[4*q+3].x, wa[8*q+6], a6);
            a7 = fma2(hv[4*q+3].y, wa[8*q+7], a7);
        }
        float argA = hsum2(add2(add2(add2(a0,a1),add2(a2,a3)),
                                add2(add2(a4,a5),add2(a6,a7))));
        float ga = rcpf(1.0f + ex2f(argA));              // sigma(own gate)
        float gz = __shfl_xor_sync(0xffffffffu, ga, 1);  // z for lane0 (slack)

        // n 64-dot (duplicated on both lanes); acc seeded with bias
        u64 n0 = nb0;
        u64 n1=0,n2=0,n3=0,n4=0,n5=0,n6=0,n7=0;
        #pragma unroll
        for (int q = 0; q < 4; q++) {
            n0 = fma2(hv[4*q].x,   wn[8*q],   n0);
            n1 = fma2(hv[4*q].y,   wn[8*q+1], n1);
            n2 = fma2(hv[4*q+1].x, wn[8*q+2], n2);
            n3 = fma2(hv[4*q+1].y, wn[8*q+3], n3);
            n4 = fma2(hv[4*q+2].x, wn[8*q+4], n4);
            n5 = fma2(hv[4*q+2].y, wn[8*q+5], n5);
            n6 = fma2(hv[4*q+3].x, wn[8*q+6], n6);
            n7 = fma2(hv[4*q+3].y, wn[8*q+7], n7);
        }
        float hn2 = hsum2(add2(add2(add2(n0,n1),add2(n2,n3)),
                               add2(add2(n4,n5),add2(n6,n7))));  // 2log2e*hn

        // off-chain (ready before R): A = 1 + z(h-1), gzm2 = 2z-2
        float A    = fmaf(gz, hm1, 1.0f);
        float gzm2 = fmaf(2.0f, gz, -2.0f);

        // chain: e2 -> R -> hnew (single FMA tail)
        float e2 = ex2f(fmaf(ga, hn2, xn2));
        float R  = rcpf(e2 + 1.0f);
        float hnew = fmaf(gzm2, R, A);                   // (1-z)tanh + z*h
        hprev = hnew;

        if (!p) {
            hd[i] = hnew;
            __stcs(sp, hnew);
        }
        sp += HID;
        __syncthreads();
    };

    for (int c = 0; c < nch; c++) {
        if (c + 1 < nch) {  // prefetch next x chunk: one branch per 2048 steps
            const float4* src = (const float4*)(xrow + (size_t)(c + 1) * CHUNK);
            float4* dst = (float4*)xs[(c + 1) & 1];
            #pragma unroll
            for (int q = 0; q < CHUNK / 4 / 128; q++) dst[tid + q * 128] = src[tid + q * 128];
        }
        const float* xc = xs[c & 1];

        // block-0 x-terms (once per chunk, outside the hot loop)
        float xa[8], xn[8];
        #pragma unroll
        for (int k = 0; k < 8; k++) {
            float xt = xc[k];
            xa[k] = fmaf(xt, wihaL, caL);
            xn[k] = fmaf(xt, wihn2, bihn2);
        }

        for (int tl = 0; tl < CHUNK; tl += 8) {
            step(hbuf[0], hbuf[1], xa[0], xn[0]);
            step(hbuf[1], hbuf[0], xa[1], xn[1]);
            step(hbuf[0], hbuf[1], xa[2], xn[2]);
            step(hbuf[1], hbuf[0], xa[3], xn[3]);
            step(hbuf[0], hbuf[1], xa[4], xn[4]);
            step(hbuf[1], hbuf[0], xa[5], xn[5]);

            // next block's x-terms: independent work, sinks into the late
            // steps' MUFU slack (wrap-indexed so the loop stays branch-free;
            // wrapped values are dead at loop exit)
            float nxa[8], nxn[8];
            #pragma unroll
            for (int k = 0; k < 8; k++) {
                float xt = xc[(tl + 8 + k) & CMASK];
                nxa[k] = fmaf(xt, wihaL, caL);
                nxn[k] = fmaf(xt, wihn2, bihn2);
            }

            step(hbuf[0], hbuf[1], xa[6], xn[6]);
            step(hbuf[1], hbuf[0], xa[7], xn[7]);

            #pragma unroll
            for (int k = 0; k < 8; k++) { xa[k] = nxa[k]; xn[k] = nxn[k]; }
        }
    }
}

// out[n] = dot(states[n,:], w_lin) + b_lin + x[n]
#define HROWS 128
#define HPAD  65
__global__ void __launch_bounds__(128, 4)
head_kernel(const float* __restrict__ st, const float* __restrict__ x,
            const float* __restrict__ wl, const float* __restrict__ bl,
            float* __restrict__ out, int BT)
{
    __shared__ float tile[HROWS * HPAD];
    __shared__ float wsh[HID];

    const int tid = threadIdx.x;
    const size_t row0 = (size_t)blockIdx.x * HROWS;

    if (tid < HID) wsh[tid] = wl[tid];

    const float4* src = (const float4*)(st + row0 * HID);
    #pragma unroll
    for (int q = 0; q < (HROWS * HID / 4) / 128; q++) {
        int f4 = tid + q * 128;
        float4 v = src[f4];
        int flat = f4 * 4;
        int r = flat >> 6;
        int c = flat & 63;
        float* drow = &tile[r * HPAD + c];
        drow[0] = v.x; drow[1] = v.y; drow[2] = v.z; drow[3] = v.w;
    }
    __syncthreads();

    const float* trow = &tile[tid * HPAD];
    float acc = 0.0f;
    #pragma unroll
    for (int k = 0; k < HID; k++) acc = fmaf(trow[k], wsh[k], acc);

    size_t n = row0 + tid;
    out[n] = acc + bl[0] + x[n];
}

extern "C" void kernel_launch(void* const* d_in, const int* in_sizes, int n_in,
                              void* d_out, int out_size)
{
    const float* x     = (const float*)d_in[0];
    const float* w_ih  = (const float*)d_in[1];
    const float* w_hh  = (const float*)d_in[2];
    const float* b_ih  = (const float*)d_in[3];
    const float* b_hh  = (const float*)d_in[4];
    const float* w_lin = (const float*)d_in[5];
    const float* b_lin = (const float*)d_in[6];

    float* out = (float*)d_out;
    const int BT = in_sizes[0];          // B * T
    const int T  = BT / BATCH;
    float* states = out + BT;            // d_out = [out | states]

    gru_kernel<<<BATCH, 128>>>(x, w_ih, w_hh, b_ih, b_hh, states, T);
    head_kernel<<<BT / HROWS, 128>>>(states, x, w_lin, b_lin, out, BT);
}